// round 9
// baseline (speedup 1.0000x reference)
#include <cuda_runtime.h>
#include <cstdint>
#include <math_constants.h>

#define BM   64
#define BN   64
#define DK   64
#define SLEN 1024
#define QLEN 1024
#define NBH  32
#define NTILE (SLEN / BN)
#define KVSTRIDE 72      // K/V tile row stride (words): conflict-free scalar B-frag LDS
#define PSTRIDE  68      // tf32 P tile row stride (words): conflict-free A-frag LDS
#define QFSTRIDE 68      // per-lane Q-frag block stride (words): 64 payload + 4 pad

#define KV_WORDS (2 * 64 * KVSTRIDE)
#define QF_WORDS (2 * 32 * QFSTRIDE)       // 2 wm groups x 32 lanes x 68 = 4352
#define PS_WORDS (64 * PSTRIDE)            // 4352
#define AB_WORDS (PS_WORDS > QF_WORDS ? PS_WORDS : QF_WORDS)
#define DYN_BYTES ((KV_WORDS + AB_WORDS) * 4)

__device__ __forceinline__ uint32_t f2tf(float x) {
    uint32_t r; asm("cvt.rna.tf32.f32 %0, %1;" : "=r"(r) : "f"(x)); return r;
}

__device__ __forceinline__ void mma_tf32(float c[4],
    uint32_t a0, uint32_t a1, uint32_t a2, uint32_t a3,
    uint32_t b0, uint32_t b1)
{
    asm volatile(
        "mma.sync.aligned.m16n8k8.row.col.f32.tf32.tf32.f32 "
        "{%0,%1,%2,%3}, {%4,%5,%6,%7}, {%8,%9}, {%0,%1,%2,%3};"
        : "+f"(c[0]), "+f"(c[1]), "+f"(c[2]), "+f"(c[3])
        : "r"(a0), "r"(a1), "r"(a2), "r"(a3), "r"(b0), "r"(b1));
}

__device__ __forceinline__ void cp16(uint32_t saddr, const void* g) {
    asm volatile("cp.async.cg.shared.global [%0], [%1], 16;" :: "r"(saddr), "l"(g));
}

__device__ __forceinline__ void tile_async(uint32_t sbase, const float* gbase,
                                           int gstride, int tid)
{
    #pragma unroll
    for (int i = 0; i < 4; i++) {
        int id  = tid + i * 256;
        int row = id >> 4, cc = (id & 15) << 2;
        cp16(sbase + (uint32_t)(row * KVSTRIDE + cc) * 4,
             gbase + (size_t)row * gstride + cc);
    }
    asm volatile("cp.async.commit_group;");
}

__global__ void __launch_bounds__(256, 4)
attn_kernel(const float* __restrict__ q, const float* __restrict__ k,
            const float* __restrict__ v, const float* __restrict__ prev,
            const float* __restrict__ scale_p,
            float* __restrict__ outO, float* __restrict__ outW,
            float* __restrict__ outS)
{
    extern __shared__ float dyn[];
    float*    kv = dyn;                         // 2 x 64 x KVSTRIDE fp32 (K or V)
    uint32_t* QP = (uint32_t*)(dyn + KV_WORDS); // phase A: Q frags; phase B: P tile
    __shared__ float rowmax[BM], rowinv[BM];
    __shared__ float pm[BM][4], pl[BM][4];

    const int tid  = threadIdx.x;
    const int bh   = blockIdx.y;
    const int m0   = blockIdx.x * BM;
    const int warp = tid >> 5, lane = tid & 31;
    const int g    = lane >> 2, t4 = lane & 3;
    const int wm   = warp & 1;                 // 2 m-groups of 32 rows
    const int wn   = warp >> 1;                // 4 n-groups of 16 cols
    const float scale = scale_p[0];

    const float* qb = q    + ((size_t)bh * QLEN + m0) * DK;
    const float* kb = k    + (size_t)bh * DK * SLEN;
    const float* vb = v    + (size_t)bh * SLEN * DK;
    const float* pb = prev + ((size_t)bh * QLEN + m0) * SLEN;
    float* sb = outS + ((size_t)bh * QLEN + m0) * SLEN;
    float* wb = outW + ((size_t)bh * QLEN + m0) * SLEN;
    float* ob = outO + ((size_t)bh * QLEN + m0) * DK;

    const uint32_t kv_s = (uint32_t)__cvta_generic_to_shared(kv);
    // 4 row bases per thread: R[ms][h] = wm*32 + ms*16 + h*8 + g
    const int R00 = wm * 32 + g, R01 = R00 + 8, R10 = R00 + 16, R11 = R00 + 24;
    const int bcol = wn * 16 + g;              // B-frag column base
    uint32_t* const myQ = QP + (wm * 32 + lane) * QFSTRIDE;

    tile_async(kv_s, kb, SLEN, tid);   // K tile 0 -> buf 0

    // ---- Q fragments packed in MMA order (rounded tf32, scale folded) ----
    if (wn == 0) {
        const float* q00 = qb + (size_t)R00 * DK;
        const float* q01 = qb + (size_t)R01 * DK;
        const float* q10 = qb + (size_t)R10 * DK;
        const float* q11 = qb + (size_t)R11 * DK;
        #pragma unroll
        for (int ks = 0; ks < 8; ks++) {
            uint4 w0, w1;
            w0.x = f2tf(q00[ks * 8 + t4]     * scale);
            w0.y = f2tf(q01[ks * 8 + t4]     * scale);
            w0.z = f2tf(q00[ks * 8 + t4 + 4] * scale);
            w0.w = f2tf(q01[ks * 8 + t4 + 4] * scale);
            w1.x = f2tf(q10[ks * 8 + t4]     * scale);
            w1.y = f2tf(q11[ks * 8 + t4]     * scale);
            w1.z = f2tf(q10[ks * 8 + t4 + 4] * scale);
            w1.w = f2tf(q11[ks * 8 + t4 + 4] * scale);
            *(uint4*)(myQ + ks * 8)     = w0;
            *(uint4*)(myQ + ks * 8 + 4) = w1;
        }
    }

    // ======== Phase A: S = Q@K + prev -> gmem, online row max/sum ========
    float mrow[4] = {-CUDART_INF_F, -CUDART_INF_F, -CUDART_INF_F, -CUDART_INF_F};
    float lrow[4] = {0.f, 0.f, 0.f, 0.f};

    #pragma unroll 1
    for (int st = 0; st < NTILE; st++) {
        const int cur = st & 1;
        if (st + 1 < NTILE) {
            tile_async(kv_s + (uint32_t)((cur ^ 1) * 64 * KVSTRIDE) * 4,
                       kb + (st + 1) * BN, SLEN, tid);
            asm volatile("cp.async.wait_group 1;");
        } else {
            asm volatile("cp.async.wait_group 0;");
        }
        __syncthreads();

        // prefetch prev, streaming (read-once)
        float2 pv[2][2][2];   // [ms][ns][h]
        #pragma unroll
        for (int ms = 0; ms < 2; ms++)
            #pragma unroll
            for (int ns = 0; ns < 2; ns++) {
                int col = st * BN + wn * 16 + ns * 8 + 2 * t4;
                int ra = wm * 32 + ms * 16 + g;
                pv[ms][ns][0] = __ldcs((const float2*)(pb + (size_t)ra * SLEN + col));
                pv[ms][ns][1] = __ldcs((const float2*)(pb + (size_t)(ra + 8) * SLEN + col));
            }

        const float* Kc = kv + cur * 64 * KVSTRIDE;
        float acc[2][2][4] = {};
        #pragma unroll
        for (int ks = 0; ks < 8; ks++) {
            uint4 a0 = *(const uint4*)(myQ + ks * 8);
            uint4 a1 = *(const uint4*)(myQ + ks * 8 + 4);
            #pragma unroll
            for (int ns = 0; ns < 2; ns++) {
                uint32_t b0 = f2tf(Kc[(ks * 8 + t4    ) * KVSTRIDE + bcol + ns * 8]);
                uint32_t b1 = f2tf(Kc[(ks * 8 + t4 + 4) * KVSTRIDE + bcol + ns * 8]);
                mma_tf32(acc[0][ns], a0.x, a0.y, a0.z, a0.w, b0, b1);
                mma_tf32(acc[1][ns], a1.x, a1.y, a1.z, a1.w, b0, b1);
            }
        }

        // epilogue: S = acc + prev, write S, online stats (4 rows/thread)
        #pragma unroll
        for (int ms = 0; ms < 2; ms++) {
            #pragma unroll
            for (int ns = 0; ns < 2; ns++) {
                int col = st * BN + wn * 16 + ns * 8 + 2 * t4;
                int ra  = wm * 32 + ms * 16 + g;
                acc[ms][ns][0] += pv[ms][ns][0].x; acc[ms][ns][1] += pv[ms][ns][0].y;
                acc[ms][ns][2] += pv[ms][ns][1].x; acc[ms][ns][3] += pv[ms][ns][1].y;
                *(float2*)(sb + (size_t)ra * SLEN + col) =
                    make_float2(acc[ms][ns][0], acc[ms][ns][1]);
                *(float2*)(sb + (size_t)(ra + 8) * SLEN + col) =
                    make_float2(acc[ms][ns][2], acc[ms][ns][3]);
            }
            // stats rows: i = ms*2 (g-row), ms*2+1 (g+8 row)
            float ta = fmaxf(fmaxf(acc[ms][0][0], acc[ms][0][1]),
                             fmaxf(acc[ms][1][0], acc[ms][1][1]));
            float tb = fmaxf(fmaxf(acc[ms][0][2], acc[ms][0][3]),
                             fmaxf(acc[ms][1][2], acc[ms][1][3]));
            float na = fmaxf(mrow[ms * 2], ta);
            float nb = fmaxf(mrow[ms * 2 + 1], tb);
            float ea = __expf(acc[ms][0][0] - na) + __expf(acc[ms][0][1] - na)
                     + __expf(acc[ms][1][0] - na) + __expf(acc[ms][1][1] - na);
            float eb = __expf(acc[ms][0][2] - nb) + __expf(acc[ms][0][3] - nb)
                     + __expf(acc[ms][1][2] - nb) + __expf(acc[ms][1][3] - nb);
            lrow[ms * 2]     = lrow[ms * 2]     * __expf(mrow[ms * 2]     - na) + ea;
            lrow[ms * 2 + 1] = lrow[ms * 2 + 1] * __expf(mrow[ms * 2 + 1] - nb) + eb;
            mrow[ms * 2] = na; mrow[ms * 2 + 1] = nb;
        }
        __syncthreads();
    }

    // ---- cross-thread softmax stat reduction (t4 shuffle, then 4 wn groups) ----
    #pragma unroll
    for (int i = 0; i < 4; i++) {
        #pragma unroll
        for (int off = 1; off <= 2; off <<= 1) {
            float om = __shfl_xor_sync(0xffffffffu, mrow[i], off);
            float ol = __shfl_xor_sync(0xffffffffu, lrow[i], off);
            float nm = fmaxf(mrow[i], om);
            lrow[i] = lrow[i] * __expf(mrow[i] - nm) + ol * __expf(om - nm);
            mrow[i] = nm;
        }
    }
    if (t4 == 0) {
        pm[R00][wn] = mrow[0]; pl[R00][wn] = lrow[0];
        pm[R01][wn] = mrow[1]; pl[R01][wn] = lrow[1];
        pm[R10][wn] = mrow[2]; pl[R10][wn] = lrow[2];
        pm[R11][wn] = mrow[3]; pl[R11][wn] = lrow[3];
    }
    __syncthreads();
    if (tid < BM) {
        float m = pm[tid][0], l = pl[tid][0];
        #pragma unroll
        for (int j = 1; j < 4; j++) {
            float om = pm[tid][j], ol = pl[tid][j];
            float nm = fmaxf(m, om);
            l = l * __expf(m - nm) + ol * __expf(om - nm);
            m = nm;
        }
        rowmax[tid] = m;
        rowinv[tid] = 1.f / l;
    }
    __syncthreads();

    // ======== Phase B (reverse order): P = softmax(S) -> gmem; O += P @ V ====
    float acc2[2][2][4] = {};
    tile_async(kv_s + (uint32_t)(((NTILE - 1) & 1) * 64 * KVSTRIDE) * 4,
               vb + (size_t)(NTILE - 1) * BN * DK, DK, tid);

    #pragma unroll 1
    for (int st = NTILE - 1; st >= 0; st--) {
        const int cur = st & 1;
        if (st > 0)
            tile_async(kv_s + (uint32_t)((cur ^ 1) * 64 * KVSTRIDE) * 4,
                       vb + (size_t)(st - 1) * BN * DK, DK, tid);

        // P tile: batched last-use S loads, exp, streaming P store, tf32 stash
        {
            float4 x[4];
            int rows[4], cs[4];
            #pragma unroll
            for (int i = 0; i < 4; i++) {
                int f4  = tid + i * 256;
                rows[i] = f4 >> 4; cs[i] = (f4 & 15) << 2;
                x[i] = __ldlu((const float4*)(sb + (size_t)rows[i] * SLEN + st * BN + cs[i]));
            }
            #pragma unroll
            for (int i = 0; i < 4; i++) {
                float mr = rowmax[rows[i]], il = rowinv[rows[i]];
                float4 p;
                p.x = __expf(x[i].x - mr) * il;
                p.y = __expf(x[i].y - mr) * il;
                p.z = __expf(x[i].z - mr) * il;
                p.w = __expf(x[i].w - mr) * il;
                __stcs((float4*)(wb + (size_t)rows[i] * SLEN + st * BN + cs[i]), p);
                uint4 w4;
                w4.x = f2tf(p.x); w4.y = f2tf(p.y); w4.z = f2tf(p.z); w4.w = f2tf(p.w);
                *(uint4*)(QP + rows[i] * PSTRIDE + cs[i]) = w4;
            }
        }

        if (st > 0) asm volatile("cp.async.wait_group 1;");
        else        asm volatile("cp.async.wait_group 0;");
        __syncthreads();

        const float* Vc = kv + cur * 64 * KVSTRIDE;
        #pragma unroll
        for (int ks = 0; ks < 8; ks++) {
            uint32_t a00 = QP[R00 * PSTRIDE + ks * 8 + t4];
            uint32_t a01 = QP[R01 * PSTRIDE + ks * 8 + t4];
            uint32_t a02 = QP[R00 * PSTRIDE + ks * 8 + t4 + 4];
            uint32_t a03 = QP[R01 * PSTRIDE + ks * 8 + t4 + 4];
            uint32_t a10 = QP[R10 * PSTRIDE + ks * 8 + t4];
            uint32_t a11 = QP[R11 * PSTRIDE + ks * 8 + t4];
            uint32_t a12 = QP[R10 * PSTRIDE + ks * 8 + t4 + 4];
            uint32_t a13 = QP[R11 * PSTRIDE + ks * 8 + t4 + 4];
            #pragma unroll
            for (int ns = 0; ns < 2; ns++) {
                uint32_t b0 = f2tf(Vc[(ks * 8 + t4    ) * KVSTRIDE + bcol + ns * 8]);
                uint32_t b1 = f2tf(Vc[(ks * 8 + t4 + 4) * KVSTRIDE + bcol + ns * 8]);
                mma_tf32(acc2[0][ns], a00, a01, a02, a03, b0, b1);
                mma_tf32(acc2[1][ns], a10, a11, a12, a13, b0, b1);
            }
        }
        __syncthreads();
    }

    // ---- write O (streaming) ----
    #pragma unroll
    for (int ms = 0; ms < 2; ms++)
        #pragma unroll
        for (int ns = 0; ns < 2; ns++) {
            int col = wn * 16 + ns * 8 + 2 * t4;
            int ra  = wm * 32 + ms * 16 + g;
            __stcs((float2*)(ob + (size_t)ra * DK + col),
                   make_float2(acc2[ms][ns][0], acc2[ms][ns][1]));
            __stcs((float2*)(ob + (size_t)(ra + 8) * DK + col),
                   make_float2(acc2[ms][ns][2], acc2[ms][ns][3]));
        }
}

extern "C" void kernel_launch(void* const* d_in, const int* in_sizes, int n_in,
                              void* d_out, int out_size)
{
    const float* q     = (const float*)d_in[0];
    const float* k     = (const float*)d_in[1];
    const float* v     = (const float*)d_in[2];
    const float* prev  = (const float*)d_in[3];
    const float* scale = (const float*)d_in[4];

    float* out  = (float*)d_out;
    float* outO = out;                                   // [2,16,1024,64]
    float* outW = out + (size_t)NBH * QLEN * DK;         // [2,16,1024,1024]
    float* outS = outW + (size_t)NBH * QLEN * SLEN;      // [2,16,1024,1024]

    cudaFuncSetAttribute(attn_kernel,
                         cudaFuncAttributeMaxDynamicSharedMemorySize, DYN_BYTES);
    dim3 grid(QLEN / BM, NBH);
    attn_kernel<<<grid, 256, DYN_BYTES>>>(q, k, v, prev, scale, outO, outW, outS);
}

// round 11
// speedup vs baseline: 1.1086x; 1.1086x over previous
#include <cuda_runtime.h>
#include <cstdint>
#include <math_constants.h>

#define BM   64
#define BN   64
#define DK   64
#define SLEN 1024
#define QLEN 1024
#define NBH  32
#define NTILE (SLEN / BN)
#define KVSTRIDE 72      // K/V tile row stride (words): conflict-free scalar B-frag LDS
#define PSTRIDE  68      // tf32 P tile row stride (words): conflict-free A-frag LDS
#define QFSTRIDE 36      // per-lane Q-fragment block stride (words)

#define KV_WORDS (2 * 64 * KVSTRIDE)
#define QF_WORDS (4 * 32 * QFSTRIDE)
#define PS_WORDS (64 * PSTRIDE)
#define AB_WORDS (PS_WORDS > QF_WORDS ? PS_WORDS : QF_WORDS)
#define DYN_BYTES ((KV_WORDS + AB_WORDS) * 4)

__device__ __forceinline__ uint32_t f2tf(float x) {
    uint32_t r; asm("cvt.rna.tf32.f32 %0, %1;" : "=r"(r) : "f"(x)); return r;
}

__device__ __forceinline__ void mma_tf32(float c[4],
    uint32_t a0, uint32_t a1, uint32_t a2, uint32_t a3,
    uint32_t b0, uint32_t b1)
{
    asm volatile(
        "mma.sync.aligned.m16n8k8.row.col.f32.tf32.tf32.f32 "
        "{%0,%1,%2,%3}, {%4,%5,%6,%7}, {%8,%9}, {%0,%1,%2,%3};"
        : "+f"(c[0]), "+f"(c[1]), "+f"(c[2]), "+f"(c[3])
        : "r"(a0), "r"(a1), "r"(a2), "r"(a3), "r"(b0), "r"(b1));
}

__device__ __forceinline__ void cp16(uint32_t saddr, const void* g) {
    asm volatile("cp.async.cg.shared.global [%0], [%1], 16;" :: "r"(saddr), "l"(g));
}

__device__ __forceinline__ void tile_async(uint32_t sbase, const float* gbase,
                                           int gstride, int tid)
{
    #pragma unroll
    for (int i = 0; i < 4; i++) {
        int id  = tid + i * 256;
        int row = id >> 4, cc = (id & 15) << 2;
        cp16(sbase + (uint32_t)(row * KVSTRIDE + cc) * 4,
             gbase + (size_t)row * gstride + cc);
    }
    asm volatile("cp.async.commit_group;");
}

__global__ void __launch_bounds__(256, 4)
attn_kernel(const float* __restrict__ q, const float* __restrict__ k,
            const float* __restrict__ v, const float* __restrict__ prev,
            const float* __restrict__ scale_p,
            float* __restrict__ outO, float* __restrict__ outW,
            float* __restrict__ outS)
{
    extern __shared__ float dyn[];
    float*    kv = dyn;                         // 2 x 64 x KVSTRIDE fp32 (K or V)
    uint32_t* QP = (uint32_t*)(dyn + KV_WORDS); // phase A: Q frags; phase B: P tile
    __shared__ float rowmax[BM], rowinv[BM];
    __shared__ float pm[BM][2], pl[BM][2];

    const int tid  = threadIdx.x;
    const int bh   = blockIdx.y;
    const int m0   = blockIdx.x * BM;
    const int warp = tid >> 5, lane = tid & 31;
    const int g    = lane >> 2, t4 = lane & 3;
    const int wm   = warp & 3;
    const int wn   = warp >> 2;
    const float scale = scale_p[0];

    const float* qb = q    + ((size_t)bh * QLEN + m0) * DK;
    const float* kb = k    + (size_t)bh * DK * SLEN;
    const float* vb = v    + (size_t)bh * SLEN * DK;
    const float* pb = prev + ((size_t)bh * QLEN + m0) * SLEN;
    float* sb = outS + ((size_t)bh * QLEN + m0) * SLEN;
    float* wb = outW + ((size_t)bh * QLEN + m0) * SLEN;
    float* ob = outO + ((size_t)bh * QLEN + m0) * DK;

    const uint32_t kv_s = (uint32_t)__cvta_generic_to_shared(kv);
    const int r0 = wm * 16 + g, r1 = r0 + 8;
    const int bcol = wn * 32 + g;
    uint32_t* const myQ = QP + (wm * 32 + lane) * QFSTRIDE;

    tile_async(kv_s, kb, SLEN, tid);   // K tile 0 -> buf 0

    // ---- Q fragments into smem in MMA order (rounded tf32, scale folded) ----
    if (wn == 0) {
        const float* q0 = qb + (size_t)r0 * DK;
        const float* q1 = qb + (size_t)r1 * DK;
        #pragma unroll
        for (int ks = 0; ks < 8; ks++) {
            uint4 w;
            w.x = f2tf(q0[ks * 8 + t4]     * scale);
            w.y = f2tf(q1[ks * 8 + t4]     * scale);
            w.z = f2tf(q0[ks * 8 + t4 + 4] * scale);
            w.w = f2tf(q1[ks * 8 + t4 + 4] * scale);
            *(uint4*)(myQ + ks * 4) = w;
        }
    }

    // prologue: K tile 0 visible to all
    asm volatile("cp.async.wait_group 0;");
    __syncthreads();

    // ======== Phase A: S = Q@K + prev -> gmem, online row max/sum ========
    // ONE barrier per tile: [issue K(st+1) | MMA(st) | epilogue | wait | bar]
    float m0r = -CUDART_INF_F, m1r = -CUDART_INF_F, l0r = 0.f, l1r = 0.f;

    #pragma unroll 1
    for (int st = 0; st < NTILE; st++) {
        const int cur = st & 1;
        if (st + 1 < NTILE)
            tile_async(kv_s + (uint32_t)((cur ^ 1) * 64 * KVSTRIDE) * 4,
                       kb + (st + 1) * BN, SLEN, tid);

        // prefetch prev, streaming (read-once)
        float2 pv0[4], pv1[4];
        #pragma unroll
        for (int nt = 0; nt < 4; nt++) {
            int col = st * BN + wn * 32 + nt * 8 + 2 * t4;
            pv0[nt] = __ldcs((const float2*)(pb + (size_t)r0 * SLEN + col));
            pv1[nt] = __ldcs((const float2*)(pb + (size_t)r1 * SLEN + col));
        }

        const float* Kc = kv + cur * 64 * KVSTRIDE;
        float acc[4][4] = {};
        #pragma unroll
        for (int ks = 0; ks < 8; ks++) {
            uint4 a = *(const uint4*)(myQ + ks * 4);
            #pragma unroll
            for (int nt = 0; nt < 4; nt++) {
                uint32_t b0 = f2tf(Kc[(ks * 8 + t4    ) * KVSTRIDE + bcol + nt * 8]);
                uint32_t b1 = f2tf(Kc[(ks * 8 + t4 + 4) * KVSTRIDE + bcol + nt * 8]);
                mma_tf32(acc[nt], a.x, a.y, a.z, a.w, b0, b1);
            }
        }

        // epilogue in-place: S = acc + prev, write S, online stats
        #pragma unroll
        for (int nt = 0; nt < 4; nt++) {
            int col = st * BN + wn * 32 + nt * 8 + 2 * t4;
            acc[nt][0] += pv0[nt].x; acc[nt][1] += pv0[nt].y;
            acc[nt][2] += pv1[nt].x; acc[nt][3] += pv1[nt].y;
            *(float2*)(sb + (size_t)r0 * SLEN + col) = make_float2(acc[nt][0], acc[nt][1]);
            *(float2*)(sb + (size_t)r1 * SLEN + col) = make_float2(acc[nt][2], acc[nt][3]);
        }
        float tm0 = acc[0][0], tm1 = acc[0][2];
        #pragma unroll
        for (int nt = 0; nt < 4; nt++) {
            tm0 = fmaxf(tm0, fmaxf(acc[nt][0], acc[nt][1]));
            tm1 = fmaxf(tm1, fmaxf(acc[nt][2], acc[nt][3]));
        }
        float nm0 = fmaxf(m0r, tm0), nm1 = fmaxf(m1r, tm1);
        float e0 = 0.f, e1 = 0.f;
        #pragma unroll
        for (int nt = 0; nt < 4; nt++) {
            e0 += __expf(acc[nt][0] - nm0) + __expf(acc[nt][1] - nm0);
            e1 += __expf(acc[nt][2] - nm1) + __expf(acc[nt][3] - nm1);
        }
        l0r = l0r * __expf(m0r - nm0) + e0;
        l1r = l1r * __expf(m1r - nm1) + e1;
        m0r = nm0; m1r = nm1;

        // next tile's copy complete, then single barrier (also fences slot reuse)
        asm volatile("cp.async.wait_group 0;");
        __syncthreads();
    }

    // ---- cross-thread softmax stat reduction ----
    #pragma unroll
    for (int off = 1; off <= 2; off <<= 1) {
        float om = __shfl_xor_sync(0xffffffffu, m0r, off);
        float ol = __shfl_xor_sync(0xffffffffu, l0r, off);
        float nm = fmaxf(m0r, om);
        l0r = l0r * __expf(m0r - nm) + ol * __expf(om - nm);
        m0r = nm;
        om = __shfl_xor_sync(0xffffffffu, m1r, off);
        ol = __shfl_xor_sync(0xffffffffu, l1r, off);
        nm = fmaxf(m1r, om);
        l1r = l1r * __expf(m1r - nm) + ol * __expf(om - nm);
        m1r = nm;
    }
    if (t4 == 0) {
        pm[r0][wn] = m0r; pl[r0][wn] = l0r;
        pm[r1][wn] = m1r; pl[r1][wn] = l1r;
    }
    __syncthreads();
    if (tid < BM) {
        float ma = pm[tid][0], mb = pm[tid][1];
        float nm = fmaxf(ma, mb);
        float l  = pl[tid][0] * __expf(ma - nm) + pl[tid][1] * __expf(mb - nm);
        rowmax[tid] = nm;
        rowinv[tid] = 1.f / l;
    }
    __syncthreads();

    // ======== Phase B (reverse order): P = softmax(S) -> gmem; O += P @ V ====
    // S is prefetched one tile ahead into registers (only exposed read removed).
    float acc2[4][4] = {};
    const int myrow[4] = { tid >> 4, (tid + 256) >> 4, (tid + 512) >> 4, (tid + 768) >> 4 };
    const int mycol = (tid & 15) << 2;

    tile_async(kv_s + (uint32_t)(((NTILE - 1) & 1) * 64 * KVSTRIDE) * 4,
               vb + (size_t)(NTILE - 1) * BN * DK, DK, tid);  // V tile 15

    float4 xs[4];
    #pragma unroll
    for (int i = 0; i < 4; i++)
        xs[i] = __ldlu((const float4*)(sb + (size_t)myrow[i] * SLEN
                                          + (NTILE - 1) * BN + mycol));

    #pragma unroll 1
    for (int st = NTILE - 1; st >= 0; st--) {
        const int cur = st & 1;
        if (st > 0)
            tile_async(kv_s + (uint32_t)((cur ^ 1) * 64 * KVSTRIDE) * 4,
                       vb + (size_t)(st - 1) * BN * DK, DK, tid);

        // exp on prefetched S regs; streaming P store; tf32 stash
        #pragma unroll
        for (int i = 0; i < 4; i++) {
            float mr = rowmax[myrow[i]], il = rowinv[myrow[i]];
            float4 p;
            p.x = __expf(xs[i].x - mr) * il;
            p.y = __expf(xs[i].y - mr) * il;
            p.z = __expf(xs[i].z - mr) * il;
            p.w = __expf(xs[i].w - mr) * il;
            __stcs((float4*)(wb + (size_t)myrow[i] * SLEN + st * BN + mycol), p);
            uint4 w4;
            w4.x = f2tf(p.x); w4.y = f2tf(p.y); w4.z = f2tf(p.z); w4.w = f2tf(p.w);
            *(uint4*)(QP + myrow[i] * PSTRIDE + mycol) = w4;
        }

        // prefetch next tile's S (consumed next iteration, in flight across
        // wait + barrier + MMA + barrier)
        if (st > 0) {
            #pragma unroll
            for (int i = 0; i < 4; i++)
                xs[i] = __ldlu((const float4*)(sb + (size_t)myrow[i] * SLEN
                                                  + (st - 1) * BN + mycol));
        }

        asm volatile("cp.async.wait_group 0;");
        __syncthreads();   // P stash + V tile visible

        const float* Vc = kv + cur * 64 * KVSTRIDE;
        #pragma unroll
        for (int ks = 0; ks < 8; ks++) {
            uint32_t a0 = QP[r0 * PSTRIDE + ks * 8 + t4];
            uint32_t a1 = QP[r1 * PSTRIDE + ks * 8 + t4];
            uint32_t a2 = QP[r0 * PSTRIDE + ks * 8 + t4 + 4];
            uint32_t a3 = QP[r1 * PSTRIDE + ks * 8 + t4 + 4];
            #pragma unroll
            for (int nt = 0; nt < 4; nt++) {
                uint32_t b0 = f2tf(Vc[(ks * 8 + t4    ) * KVSTRIDE + bcol + nt * 8]);
                uint32_t b1 = f2tf(Vc[(ks * 8 + t4 + 4) * KVSTRIDE + bcol + nt * 8]);
                mma_tf32(acc2[nt], a0, a1, a2, a3, b0, b1);
            }
        }
        __syncthreads();   // protect P stash + V slot for next iteration
    }

    // ---- write O (streaming) ----
    #pragma unroll
    for (int nt = 0; nt < 4; nt++) {
        int col = wn * 32 + nt * 8 + 2 * t4;
        __stcs((float2*)(ob + (size_t)r0 * DK + col), make_float2(acc2[nt][0], acc2[nt][1]));
        __stcs((float2*)(ob + (size_t)r1 * DK + col), make_float2(acc2[nt][2], acc2[nt][3]));
    }
}

extern "C" void kernel_launch(void* const* d_in, const int* in_sizes, int n_in,
                              void* d_out, int out_size)
{
    const float* q     = (const float*)d_in[0];
    const float* k     = (const float*)d_in[1];
    const float* v     = (const float*)d_in[2];
    const float* prev  = (const float*)d_in[3];
    const float* scale = (const float*)d_in[4];

    float* out  = (float*)d_out;
    float* outO = out;                                   // [2,16,1024,64]
    float* outW = out + (size_t)NBH * QLEN * DK;         // [2,16,1024,1024]
    float* outS = outW + (size_t)NBH * QLEN * SLEN;      // [2,16,1024,1024]

    cudaFuncSetAttribute(attn_kernel,
                         cudaFuncAttributeMaxDynamicSharedMemorySize, DYN_BYTES);
    dim3 grid(QLEN / BM, NBH);
    attn_kernel<<<grid, 256, DYN_BYTES>>>(q, k, v, prev, scale, outO, outW, outS);
}